// round 13
// baseline (speedup 1.0000x reference)
#include <cuda_runtime.h>

#define NN 100000
#define EE 3200000
#define FIN 128
#define CAP 128                // fixed bucket capacity per node
#define GEMM1_BLKS 782         // ceil(NN/128)
#define HIST_BLKS 1563         // ceil(EE/2048), 8 edges/thread
#define L2E 1.44269504f

// ---------------- scratch (static device globals; no allocs) ----------------
__device__ int   g_cnt[NN];          // zero at load; re-zeroed by k_edge2h
__device__ int   g_srcs[NN * CAP];   // fixed-capacity CSR buckets
__device__ int   g_ovf_cnt;          // overflow count (build writes, gemm2 swaps)
__device__ int   g_ovf_cnt2;         // snapshot for edge2h
__device__ int   g_ovfd[EE];         // overflow dst (cold)
__device__ int   g_ovfs[EE];         // overflow src (cold)
__device__ float g_xl1[NN * 16];
__device__ float g_xr1[NN * 16];
__device__ float g_lin1[NN * 16];
__device__ float g_h[NN * 16];
__device__ float g_xl2[NN * 8];
__device__ float g_xr2[NN * 8];
__device__ float g_lin2[NN * 8];

__device__ __forceinline__ float ex2f(float x) {
    float y; asm("ex2.approx.f32 %0, %1;" : "=f"(y) : "f"(x)); return y;
}

__device__ __forceinline__ void scatter_one(int d, int s) {
    int r = atomicAdd(&g_cnt[d], 1);
    if (r < CAP) {
        g_srcs[d * CAP + r] = s;
    } else {
        int o = atomicAdd(&g_ovf_cnt, 1);
        g_ovfd[o] = d;
        g_ovfs[o] = s;
    }
}

// ---- fused build: layer-1 GEMM (blocks 0..781) + bucket scatter (rest) -----
__global__ void __launch_bounds__(256) k_build(
    const int* __restrict__ src, const int* __restrict__ dst,
    const float* __restrict__ x, const float* __restrict__ Wl,
    const float* __restrict__ Wr, const float* __restrict__ Wlin,
    const float* __restrict__ blin)
{
    __shared__ float sx[128][36];
    __shared__ float sw[32][48];
    int t = threadIdx.x;
    int b = blockIdx.x;

    if (b >= GEMM1_BLKS) {
        int bb = b - GEMM1_BLKS;
        int e0 = bb * 2048 + t * 4;
        int e1 = e0 + 1024;
        bool v0 = e0 < EE, v1 = e1 < EE;
        int4 d0, s0, d1, s1;
        if (v0) { d0 = *(const int4*)(dst + e0); s0 = *(const int4*)(src + e0); }
        if (v1) { d1 = *(const int4*)(dst + e1); s1 = *(const int4*)(src + e1); }
        if (v0) {
            scatter_one(d0.x, s0.x);
            scatter_one(d0.y, s0.y);
            scatter_one(d0.z, s0.z);
            scatter_one(d0.w, s0.w);
        }
        if (v1) {
            scatter_one(d1.x, s1.x);
            scatter_one(d1.y, s1.y);
            scatter_one(d1.z, s1.z);
            scatter_one(d1.w, s1.w);
        }
        return;
    }

    int cg = t & 7, rg = t >> 3;
    int c0 = cg * 6;
    int rowbase = b * 128;
    float acc[4][6];
#pragma unroll
    for (int i = 0; i < 4; i++)
#pragma unroll
        for (int j = 0; j < 6; j++) acc[i][j] = 0.f;

    for (int kb = 0; kb < FIN; kb += 32) {
#pragma unroll
        for (int n = 0; n < 4; n++) {
            int idx = t + n * 256;
            int r = idx >> 3, k4 = idx & 7;
            int gr = rowbase + r;
            float4 val = make_float4(0.f, 0.f, 0.f, 0.f);
            if (gr < NN) val = *(const float4*)(x + gr * FIN + kb + k4 * 4);
            *(float4*)&sx[r][k4 * 4] = val;
        }
        for (int idx = t; idx < 32 * 48; idx += 256) {
            int k = idx / 48, j = idx % 48;
            int gk = kb + k;
            float val;
            if (j < 16)      val = Wl[gk * 16 + j];
            else if (j < 32) val = Wr[gk * 16 + j - 16];
            else             val = Wlin[gk * 16 + j - 32];
            sw[k][j] = val;
        }
        __syncthreads();
#pragma unroll
        for (int k = 0; k < 32; k += 4) {
            float xv[4][4];
#pragma unroll
            for (int i = 0; i < 4; i++) {
                float4 tmp = *(const float4*)&sx[rg * 4 + i][k];
                xv[i][0] = tmp.x; xv[i][1] = tmp.y; xv[i][2] = tmp.z; xv[i][3] = tmp.w;
            }
#pragma unroll
            for (int kk = 0; kk < 4; kk++) {
                float wv[6];
#pragma unroll
                for (int j = 0; j < 6; j++) wv[j] = sw[k + kk][c0 + j];
#pragma unroll
                for (int i = 0; i < 4; i++)
#pragma unroll
                    for (int j = 0; j < 6; j++)
                        acc[i][j] = fmaf(xv[i][kk], wv[j], acc[i][j]);
            }
        }
        __syncthreads();
    }
#pragma unroll
    for (int i = 0; i < 4; i++) {
        int gr = rowbase + rg * 4 + i;
        if (gr < NN) {
#pragma unroll
            for (int j = 0; j < 6; j++) {
                int c = c0 + j;
                if (c < 16)      g_xl1[gr * 16 + c] = acc[i][j];
                else if (c < 32) g_xr1[gr * 16 + (c - 16)] = acc[i][j];
                else             g_lin1[gr * 16 + (c - 32)] = acc[i][j] + blin[c - 32];
            }
        }
    }
}

// ---------------- edge kernel layer 1: warp/node, 4 lanes/edge (R10) --------
__global__ void __launch_bounds__(256) k_edge1(
    const float* __restrict__ att, const float* __restrict__ bias,
    const float* __restrict__ tptr)
{
    __shared__ float sm_p[8][CAP];
    int w = threadIdx.x >> 5;
    int lane = threadIdx.x & 31;
    int node = blockIdx.x * 8 + w;
    if (node >= NN) return;
    int q = lane & 3, e8 = lane >> 2;
    int deg = g_cnt[node];
    int degf = deg < CAP ? deg : CAP;
    const int* sp = g_srcs + node * CAP;
    float tl2e = tptr[0] * L2E;
    float4 a4 = *(const float4*)(att + q * 4);
    float4 xr = *(const float4*)(g_xr1 + node * 16 + q * 4);
    float a06x = 0.6f * L2E * a4.x, a06y = 0.6f * L2E * a4.y;
    float a06z = 0.6f * L2E * a4.z, a06w = 0.6f * L2E * a4.w;
    float a04x = 0.4f * L2E * a4.x, a04y = 0.4f * L2E * a4.y;
    float a04z = 0.4f * L2E * a4.z, a04w = 0.4f * L2E * a4.w;
    int nfull = degf >> 3, rem = degf & 7;

    float S = 0.f;
    int k = e8;
#pragma unroll 2
    for (int it = 0; it < nfull; it++, k += 8) {
        int s = sp[k];
        float4 m = *(const float4*)(g_xl1 + s * 16 + q * 4);
        float y0 = m.x + xr.x, y1 = m.y + xr.y, y2 = m.z + xr.z, y3 = m.w + xr.w;
        float sc = a06x * y0;
        sc = fmaf(a04x, fabsf(y0), sc);
        sc = fmaf(a06y, y1, sc); sc = fmaf(a04y, fabsf(y1), sc);
        sc = fmaf(a06z, y2, sc); sc = fmaf(a04z, fabsf(y2), sc);
        sc = fmaf(a06w, y3, sc); sc = fmaf(a04w, fabsf(y3), sc);
        sc += __shfl_xor_sync(0xffffffffu, sc, 1);
        sc += __shfl_xor_sync(0xffffffffu, sc, 2);
        float p = ex2f(sc);
        if (q == 0) sm_p[w][k] = p;
        S += p;
    }
    if (rem) {
        bool v = e8 < rem;
        int s = sp[v ? k : 0];
        float4 m = make_float4(0.f, 0.f, 0.f, 0.f);
        if (v) m = *(const float4*)(g_xl1 + s * 16 + q * 4);
        float y0 = m.x + xr.x, y1 = m.y + xr.y, y2 = m.z + xr.z, y3 = m.w + xr.w;
        float sc = a06x * y0;
        sc = fmaf(a04x, fabsf(y0), sc);
        sc = fmaf(a06y, y1, sc); sc = fmaf(a04y, fabsf(y1), sc);
        sc = fmaf(a06z, y2, sc); sc = fmaf(a04z, fabsf(y2), sc);
        sc = fmaf(a06w, y3, sc); sc = fmaf(a04w, fabsf(y3), sc);
        sc += __shfl_xor_sync(0xffffffffu, sc, 1);
        sc += __shfl_xor_sync(0xffffffffu, sc, 2);
        float p = v ? ex2f(sc) : 0.f;
        if (q == 0) sm_p[w][k] = p;
        S += p;
    }
    if (deg > CAP) {
        int ovfn = g_ovf_cnt;
        for (int i = 0; i < ovfn; i++) {
            if (g_ovfd[i] == node) {
                float4 m = make_float4(0.f, 0.f, 0.f, 0.f);
                if (e8 == 0) m = *(const float4*)(g_xl1 + g_ovfs[i] * 16 + q * 4);
                float y0 = m.x + xr.x, y1 = m.y + xr.y, y2 = m.z + xr.z, y3 = m.w + xr.w;
                float sc = a06x * y0;
                sc = fmaf(a04x, fabsf(y0), sc);
                sc = fmaf(a06y, y1, sc); sc = fmaf(a04y, fabsf(y1), sc);
                sc = fmaf(a06z, y2, sc); sc = fmaf(a04z, fabsf(y2), sc);
                sc = fmaf(a06w, y3, sc); sc = fmaf(a04w, fabsf(y3), sc);
                sc += __shfl_xor_sync(0xffffffffu, sc, 1);
                sc += __shfl_xor_sync(0xffffffffu, sc, 2);
                if (e8 == 0) S += ex2f(sc);
            }
        }
    }
#pragma unroll
    for (int o = 16; o; o >>= 1) S += __shfl_xor_sync(0xffffffffu, S, o);
    float rinv = __fdividef(4.f, S);   // S counted 4x per edge
    __syncwarp();

    float4 num = make_float4(0.f, 0.f, 0.f, 0.f);
    float4 den = make_float4(0.f, 0.f, 0.f, 0.f);
    k = e8;
#pragma unroll 2
    for (int it = 0; it < nfull; it++, k += 8) {
        int s = sp[k];
        float4 m = *(const float4*)(g_xl1 + s * 16 + q * 4);
        float p = sm_p[w][k];
        float a = p * rinv;
        float we = a * tl2e;
        float e0 = ex2f(m.x * we);
        float e1 = ex2f(m.y * we);
        float e2 = ex2f(m.z * we);
        float e3 = ex2f(m.w * we);
        den.x += e0; den.y += e1; den.z += e2; den.w += e3;
        num.x = fmaf(e0, m.x * a, num.x);
        num.y = fmaf(e1, m.y * a, num.y);
        num.z = fmaf(e2, m.z * a, num.z);
        num.w = fmaf(e3, m.w * a, num.w);
    }
    if (rem) {
        bool v = e8 < rem;
        float vm = v ? 1.f : 0.f;
        int s = sp[v ? k : 0];
        float4 m = make_float4(0.f, 0.f, 0.f, 0.f);
        if (v) m = *(const float4*)(g_xl1 + s * 16 + q * 4);
        float p = sm_p[w][k];
        float a = p * rinv;
        float we = a * tl2e;
        float e0 = ex2f(m.x * we) * vm;
        float e1 = ex2f(m.y * we) * vm;
        float e2 = ex2f(m.z * we) * vm;
        float e3 = ex2f(m.w * we) * vm;
        den.x += e0; den.y += e1; den.z += e2; den.w += e3;
        num.x = fmaf(e0, m.x * a, num.x);
        num.y = fmaf(e1, m.y * a, num.y);
        num.z = fmaf(e2, m.z * a, num.z);
        num.w = fmaf(e3, m.w * a, num.w);
    }
    if (deg > CAP) {
        int ovfn = g_ovf_cnt;
        for (int i = 0; i < ovfn; i++) {
            if (g_ovfd[i] == node) {
                float4 m = make_float4(0.f, 0.f, 0.f, 0.f);
                if (e8 == 0) m = *(const float4*)(g_xl1 + g_ovfs[i] * 16 + q * 4);
                float y0 = m.x + xr.x, y1 = m.y + xr.y, y2 = m.z + xr.z, y3 = m.w + xr.w;
                float sc = a06x * y0;
                sc = fmaf(a04x, fabsf(y0), sc);
                sc = fmaf(a06y, y1, sc); sc = fmaf(a04y, fabsf(y1), sc);
                sc = fmaf(a06z, y2, sc); sc = fmaf(a04z, fabsf(y2), sc);
                sc = fmaf(a06w, y3, sc); sc = fmaf(a04w, fabsf(y3), sc);
                sc += __shfl_xor_sync(0xffffffffu, sc, 1);
                sc += __shfl_xor_sync(0xffffffffu, sc, 2);
                if (e8 == 0) {
                    float p = ex2f(sc);
                    float a = p * rinv;
                    float we = a * tl2e;
                    float e0 = ex2f(m.x * we);
                    float e1 = ex2f(m.y * we);
                    float e2 = ex2f(m.z * we);
                    float e3 = ex2f(m.w * we);
                    den.x += e0; den.y += e1; den.z += e2; den.w += e3;
                    num.x = fmaf(e0, m.x * a, num.x);
                    num.y = fmaf(e1, m.y * a, num.y);
                    num.z = fmaf(e2, m.z * a, num.z);
                    num.w = fmaf(e3, m.w * a, num.w);
                }
            }
        }
    }
#pragma unroll
    for (int o = 4; o < 32; o <<= 1) {
        num.x += __shfl_xor_sync(0xffffffffu, num.x, o);
        num.y += __shfl_xor_sync(0xffffffffu, num.y, o);
        num.z += __shfl_xor_sync(0xffffffffu, num.z, o);
        num.w += __shfl_xor_sync(0xffffffffu, num.w, o);
        den.x += __shfl_xor_sync(0xffffffffu, den.x, o);
        den.y += __shfl_xor_sync(0xffffffffu, den.y, o);
        den.z += __shfl_xor_sync(0xffffffffu, den.z, o);
        den.w += __shfl_xor_sync(0xffffffffu, den.w, o);
    }
    if (e8 == 0) {
        float4 b4 = *(const float4*)(bias + q * 4);
        float4 l4 = *(const float4*)(g_lin1 + node * 16 + q * 4);
        float4 o4;
        float g0 = (den.x > 0.f) ? __fdividef(num.x, den.x) : 0.f;
        float g1 = (den.y > 0.f) ? __fdividef(num.y, den.y) : 0.f;
        float g2v = (den.z > 0.f) ? __fdividef(num.z, den.z) : 0.f;
        float g3 = (den.w > 0.f) ? __fdividef(num.w, den.w) : 0.f;
        o4.x = fmaxf(g0 + b4.x + l4.x, 0.f);
        o4.y = fmaxf(g1 + b4.y + l4.y, 0.f);
        o4.z = fmaxf(g2v + b4.z + l4.z, 0.f);
        o4.w = fmaxf(g3 + b4.w + l4.w, 0.f);
        *(float4*)(g_h + node * 16 + q * 4) = o4;
    }
}

// ---------------- layer-2 node GEMM (+ overflow counter hand-off) -----------
__global__ void __launch_bounds__(256) k_gemm2(
    const float* __restrict__ Wl, const float* __restrict__ Wr,
    const float* __restrict__ Wlin, const float* __restrict__ blin)
{
    if (blockIdx.x == 0 && threadIdx.x == 0) {
        g_ovf_cnt2 = g_ovf_cnt;
        g_ovf_cnt = 0;
    }
    __shared__ float sw[16 * 24];
    int t = threadIdx.x;
    for (int idx = t; idx < 16 * 24; idx += 256) {
        int k = idx / 24, j = idx % 24;
        float v;
        if (j < 8)       v = Wl[k * 8 + j];
        else if (j < 16) v = Wr[k * 8 + j - 8];
        else             v = Wlin[k * 8 + j - 16];
        sw[idx] = v;
    }
    __syncthreads();
    int i = blockIdx.x * blockDim.x + t;
    if (i >= NN) return;
    const float4* hp = (const float4*)(g_h + i * 16);
    float4 q0 = hp[0], q1 = hp[1], q2 = hp[2], q3 = hp[3];
    float h[16] = {q0.x, q0.y, q0.z, q0.w, q1.x, q1.y, q1.z, q1.w,
                   q2.x, q2.y, q2.z, q2.w, q3.x, q3.y, q3.z, q3.w};
    float acc[24];
#pragma unroll
    for (int j = 0; j < 24; j++) acc[j] = 0.f;
#pragma unroll
    for (int k = 0; k < 16; k++) {
        float hv = h[k];
#pragma unroll
        for (int j = 0; j < 24; j++) acc[j] = fmaf(hv, sw[k * 24 + j], acc[j]);
    }
#pragma unroll
    for (int j = 0; j < 8; j++) {
        g_xl2[i * 8 + j] = acc[j];
        g_xr2[i * 8 + j] = acc[8 + j];
        g_lin2[i * 8 + j] = acc[16 + j] + blin[j];
    }
}

// ------- edge layer 2: HALF-WARP per node (2 nodes/warp), fused MLP head ----
// 16 lanes per node: q = hl&1 (4 channels), e8 = hl>>1 (8 edges/group).
// All shuffles masked to the half (hm); NN % 16 == 0 so no guards needed.
__global__ void __launch_bounds__(256) k_edge2h(
    const float* __restrict__ att, const float* __restrict__ bias,
    const float* __restrict__ tptr,
    const float* __restrict__ W3, const float* __restrict__ b3,
    const float* __restrict__ W4, const float* __restrict__ b4,
    const float* __restrict__ W5, const float* __restrict__ b5,
    const float* __restrict__ Wout, const float* __restrict__ bout,
    float* __restrict__ out)
{
    __shared__ float sm_p[8][2][CAP];
    int lane = threadIdx.x & 31;
    int warp = threadIdx.x >> 5;
    int half = lane >> 4;
    int hl = lane & 15;
    unsigned hm = 0xFFFFu << (half * 16);
    int node = blockIdx.x * 16 + warp * 2 + half;   // NN % 16 == 0
    int q = hl & 1, e8 = hl >> 1;
    int deg = g_cnt[node];
    if (hl == 0) g_cnt[node] = 0;   // reset for next launch
    int degf = deg < CAP ? deg : CAP;
    const int* sp = g_srcs + node * CAP;
    float* smp = sm_p[warp][half];
    float tl2e = tptr[0] * L2E;
    float4 a4 = *(const float4*)(att + q * 4);
    float4 xr = *(const float4*)(g_xr2 + node * 8 + q * 4);
    float a06x = 0.6f * L2E * a4.x, a06y = 0.6f * L2E * a4.y;
    float a06z = 0.6f * L2E * a4.z, a06w = 0.6f * L2E * a4.w;
    float a04x = 0.4f * L2E * a4.x, a04y = 0.4f * L2E * a4.y;
    float a04z = 0.4f * L2E * a4.z, a04w = 0.4f * L2E * a4.w;
    int ngroups = (degf + 7) >> 3;   // groups of 8 edges (kk max 127 < CAP)

    // ---- pass 1: scores -> p (smem), accumulate S ----
    float S = 0.f;
    for (int it = 0; it < ngroups; it++) {
        int kk = it * 8 + e8;
        bool v = kk < degf;
        int s = sp[v ? kk : 0];
        float4 m = make_float4(0.f, 0.f, 0.f, 0.f);
        if (v) m = *(const float4*)(g_xl2 + s * 8 + q * 4);
        float y0 = m.x + xr.x, y1 = m.y + xr.y, y2 = m.z + xr.z, y3 = m.w + xr.w;
        float sc = a06x * y0;
        sc = fmaf(a04x, fabsf(y0), sc);
        sc = fmaf(a06y, y1, sc); sc = fmaf(a04y, fabsf(y1), sc);
        sc = fmaf(a06z, y2, sc); sc = fmaf(a04z, fabsf(y2), sc);
        sc = fmaf(a06w, y3, sc); sc = fmaf(a04w, fabsf(y3), sc);
        sc += __shfl_xor_sync(hm, sc, 1);
        float p = v ? ex2f(sc) : 0.f;
        if (q == 0) smp[kk] = p;
        S += p;
    }
    // ---- pass 1: overflow list (cold) ----
    if (deg > CAP) {
        int ovfn = g_ovf_cnt2;
        for (int i = 0; i < ovfn; i++) {
            if (g_ovfd[i] == node) {
                float4 m = make_float4(0.f, 0.f, 0.f, 0.f);
                if (e8 == 0) m = *(const float4*)(g_xl2 + g_ovfs[i] * 8 + q * 4);
                float y0 = m.x + xr.x, y1 = m.y + xr.y, y2 = m.z + xr.z, y3 = m.w + xr.w;
                float sc = a06x * y0;
                sc = fmaf(a04x, fabsf(y0), sc);
                sc = fmaf(a06y, y1, sc); sc = fmaf(a04y, fabsf(y1), sc);
                sc = fmaf(a06z, y2, sc); sc = fmaf(a04z, fabsf(y2), sc);
                sc = fmaf(a06w, y3, sc); sc = fmaf(a04w, fabsf(y3), sc);
                sc += __shfl_xor_sync(hm, sc, 1);
                if (hl == 0) S += ex2f(sc);   // count once
            }
        }
    }
#pragma unroll
    for (int o = 8; o >= 2; o >>= 1) S += __shfl_xor_sync(hm, S, o);
    float rinv = __fdividef(1.f, S);   // each edge counted once per lane-set
    __syncwarp();

    // ---- pass 2: re-gather m (L1-hot) + fused softmax-agg ----
    float4 num = make_float4(0.f, 0.f, 0.f, 0.f);
    float4 den = make_float4(0.f, 0.f, 0.f, 0.f);
    for (int it = 0; it < ngroups; it++) {
        int kk = it * 8 + e8;
        bool v = kk < degf;
        float vm = v ? 1.f : 0.f;
        int s = sp[v ? kk : 0];
        float4 m = make_float4(0.f, 0.f, 0.f, 0.f);
        if (v) m = *(const float4*)(g_xl2 + s * 8 + q * 4);
        float p = smp[kk];
        float a = p * rinv;
        float we = a * tl2e;
        float e0 = ex2f(m.x * we) * vm;
        float e1 = ex2f(m.y * we) * vm;
        float e2 = ex2f(m.z * we) * vm;
        float e3 = ex2f(m.w * we) * vm;
        den.x += e0; den.y += e1; den.z += e2; den.w += e3;
        num.x = fmaf(e0, m.x * a, num.x);
        num.y = fmaf(e1, m.y * a, num.y);
        num.z = fmaf(e2, m.z * a, num.z);
        num.w = fmaf(e3, m.w * a, num.w);
    }
    // ---- pass 2: overflow list (cold) ----
    if (deg > CAP) {
        int ovfn = g_ovf_cnt2;
        for (int i = 0; i < ovfn; i++) {
            if (g_ovfd[i] == node) {
                float4 m = make_float4(0.f, 0.f, 0.f, 0.f);
                if (e8 == 0) m = *(const float4*)(g_xl2 + g_ovfs[i] * 8 + q * 4);
                float y0 = m.x + xr.x, y1 = m.y + xr.y, y2 = m.z + xr.z, y3 = m.w + xr.w;
                float sc = a06x * y0;
                sc = fmaf(a04x, fabsf(y0), sc);
                sc = fmaf(a06y, y1, sc); sc = fmaf(a04y, fabsf(y1), sc);
                sc = fmaf(a06z, y2, sc); sc = fmaf(a04z, fabsf(y2), sc);
                sc = fmaf(a06w, y3, sc); sc = fmaf(a04w, fabsf(y3), sc);
                sc += __shfl_xor_sync(hm, sc, 1);
                if (e8 == 0) {   // both q lanes accumulate their channels
                    float p = ex2f(sc);
                    float a = p * rinv;
                    float we = a * tl2e;
                    float e0 = ex2f(m.x * we);
                    float e1 = ex2f(m.y * we);
                    float e2 = ex2f(m.z * we);
                    float e3 = ex2f(m.w * we);
                    den.x += e0; den.y += e1; den.z += e2; den.w += e3;
                    num.x = fmaf(e0, m.x * a, num.x);
                    num.y = fmaf(e1, m.y * a, num.y);
                    num.z = fmaf(e2, m.z * a, num.z);
                    num.w = fmaf(e3, m.w * a, num.w);
                }
            }
        }
    }
#pragma unroll
    for (int o = 2; o <= 8; o <<= 1) {
        num.x += __shfl_xor_sync(hm, num.x, o);
        num.y += __shfl_xor_sync(hm, num.y, o);
        num.z += __shfl_xor_sync(hm, num.z, o);
        num.w += __shfl_xor_sync(hm, num.w, o);
        den.x += __shfl_xor_sync(hm, den.x, o);
        den.y += __shfl_xor_sync(hm, den.y, o);
        den.z += __shfl_xor_sync(hm, den.z, o);
        den.w += __shfl_xor_sync(hm, den.w, o);
    }

    // ---- fused head: lanes pair via q within half ----
    float4 b4v = *(const float4*)(bias + q * 4);
    float4 l4 = *(const float4*)(g_lin2 + node * 8 + q * 4);
    float hq[4];
    {
        float g0 = (den.x > 0.f) ? __fdividef(num.x, den.x) : 0.f;
        float g1 = (den.y > 0.f) ? __fdividef(num.y, den.y) : 0.f;
        float g2v = (den.z > 0.f) ? __fdividef(num.z, den.z) : 0.f;
        float g3 = (den.w > 0.f) ? __fdividef(num.w, den.w) : 0.f;
        hq[0] = fmaxf(g0 + b4v.x + l4.x, 0.f);
        hq[1] = fmaxf(g1 + b4v.y + l4.y, 0.f);
        hq[2] = fmaxf(g2v + b4v.z + l4.z, 0.f);
        hq[3] = fmaxf(g3 + b4v.w + l4.w, 0.f);
    }
    float part[8];
#pragma unroll
    for (int c = 0; c < 8; c++) {
        float acc = 0.f;
#pragma unroll
        for (int j = 0; j < 4; j++)
            acc = fmaf(hq[j], W3[(4 * q + j) * 8 + c], acc);
        part[c] = acc;
    }
#pragma unroll
    for (int c = 0; c < 8; c++)
        part[c] += __shfl_xor_sync(hm, part[c], 1);
    if (hl == 0) {
        float s4 = b4[0];
#pragma unroll
        for (int c = 0; c < 8; c++) {
            float z = part[c] + b3[c];
            z = z > 0.f ? z : 0.f;
            s4 = fmaf(z, W4[c], s4);
        }
        s4 = s4 > 0.f ? s4 : 0.f;
        float s5 = W5[0] * s4 + b5[0];
        s5 = s5 > 0.f ? s5 : 0.f;
        float xo = Wout[0] * s5 + bout[0];
        float ls = (xo >= 0.f) ? -log1pf(expf(-xo)) : (xo - log1pf(expf(xo)));
        out[node] = ls;
    }
}

// ---------------- launch ----------------
extern "C" void kernel_launch(void* const* d_in, const int* in_sizes, int n_in,
                              void* d_out, int out_size)
{
    const float* x    = (const float*)d_in[0];
    const int*   ei   = (const int*)d_in[1];
    const int*   src  = ei;
    const int*   dst  = ei + EE;
    const float* Wl1  = (const float*)d_in[3];
    const float* Wr1  = (const float*)d_in[4];
    const float* att1 = (const float*)d_in[5];
    const float* b1   = (const float*)d_in[6];
    const float* Wlin1= (const float*)d_in[7];
    const float* blin1= (const float*)d_in[8];
    const float* Wl2  = (const float*)d_in[9];
    const float* Wr2  = (const float*)d_in[10];
    const float* att2 = (const float*)d_in[11];
    const float* b2   = (const float*)d_in[12];
    const float* Wlin2= (const float*)d_in[13];
    const float* blin2= (const float*)d_in[14];
    const float* t    = (const float*)d_in[15];
    const float* W3   = (const float*)d_in[16];
    const float* b3   = (const float*)d_in[17];
    const float* W4   = (const float*)d_in[18];
    const float* b4   = (const float*)d_in[19];
    const float* W5   = (const float*)d_in[20];
    const float* b5   = (const float*)d_in[21];
    const float* Wout = (const float*)d_in[22];
    const float* bout = (const float*)d_in[23];
    float* out = (float*)d_out;

    // 0: fused layer-1 GEMM + MLP-8 bucket scatter
    k_build<<<GEMM1_BLKS + HIST_BLKS, 256>>>(src, dst, x, Wl1, Wr1, Wlin1, blin1);
    // 1: edge layer 1
    k_edge1<<<(NN + 7) / 8, 256>>>(att1, b1, t);
    // 2: layer-2 GEMM (pool is identity) + overflow counter hand-off
    k_gemm2<<<(NN + 255) / 256, 256>>>(Wl2, Wr2, Wlin2, blin2);
    // 3: edge layer 2 (2 nodes/warp) + fused MLP head
    k_edge2h<<<NN / 16, 256>>>(att2, b2, t, W3, b3, W4, b4, W5, b5, Wout, bout, out);
}

// round 14
// speedup vs baseline: 1.0621x; 1.0621x over previous
#include <cuda_runtime.h>

#define NN 100000
#define EE 3200000
#define FIN 128
#define CAP 128                // fixed bucket capacity per node
#define GEMM1_BLKS 782         // ceil(NN/128)
#define HIST_BLKS 1563         // ceil(EE/2048), 8 edges/thread
#define L2E 1.44269504f

// ---------------- scratch (static device globals; no allocs) ----------------
__device__ int   g_cnt[NN];          // zero at load; re-zeroed by k_edge2h
__device__ int   g_srcs[NN * CAP];   // fixed-capacity CSR buckets
__device__ int   g_ovf_cnt;          // overflow count (build writes, gemm2 swaps)
__device__ int   g_ovf_cnt2;         // snapshot for edge2h
__device__ int   g_ovfd[EE];         // overflow dst (cold)
__device__ int   g_ovfs[EE];         // overflow src (cold)
__device__ float g_xl1[NN * 16];
__device__ float g_xr1[NN * 16];
__device__ float g_lin1[NN * 16];
__device__ float g_h[NN * 16];
__device__ float g_xl2[NN * 8];
__device__ float g_xr2[NN * 8];
__device__ float g_lin2[NN * 8];

__device__ __forceinline__ float ex2f(float x) {
    float y; asm("ex2.approx.f32 %0, %1;" : "=f"(y) : "f"(x)); return y;
}

__device__ __forceinline__ void scatter_one(int d, int s) {
    int r = atomicAdd(&g_cnt[d], 1);
    if (r < CAP) {
        g_srcs[d * CAP + r] = s;
    } else {
        int o = atomicAdd(&g_ovf_cnt, 1);
        g_ovfd[o] = d;
        g_ovfs[o] = s;
    }
}

// ---- fused build: layer-1 GEMM (blocks 0..781) + bucket scatter (rest) -----
__global__ void __launch_bounds__(256) k_build(
    const int* __restrict__ src, const int* __restrict__ dst,
    const float* __restrict__ x, const float* __restrict__ Wl,
    const float* __restrict__ Wr, const float* __restrict__ Wlin,
    const float* __restrict__ blin)
{
    __shared__ float sx[128][36];
    __shared__ float sw[32][48];
    int t = threadIdx.x;
    int b = blockIdx.x;

    if (b >= GEMM1_BLKS) {
        int bb = b - GEMM1_BLKS;
        int e0 = bb * 2048 + t * 4;
        int e1 = e0 + 1024;
        bool v0 = e0 < EE, v1 = e1 < EE;
        int4 d0, s0, d1, s1;
        if (v0) { d0 = *(const int4*)(dst + e0); s0 = *(const int4*)(src + e0); }
        if (v1) { d1 = *(const int4*)(dst + e1); s1 = *(const int4*)(src + e1); }
        if (v0) {
            scatter_one(d0.x, s0.x);
            scatter_one(d0.y, s0.y);
            scatter_one(d0.z, s0.z);
            scatter_one(d0.w, s0.w);
        }
        if (v1) {
            scatter_one(d1.x, s1.x);
            scatter_one(d1.y, s1.y);
            scatter_one(d1.z, s1.z);
            scatter_one(d1.w, s1.w);
        }
        return;
    }

    int cg = t & 7, rg = t >> 3;
    int c0 = cg * 6;
    int rowbase = b * 128;
    float acc[4][6];
#pragma unroll
    for (int i = 0; i < 4; i++)
#pragma unroll
        for (int j = 0; j < 6; j++) acc[i][j] = 0.f;

    for (int kb = 0; kb < FIN; kb += 32) {
#pragma unroll
        for (int n = 0; n < 4; n++) {
            int idx = t + n * 256;
            int r = idx >> 3, k4 = idx & 7;
            int gr = rowbase + r;
            float4 val = make_float4(0.f, 0.f, 0.f, 0.f);
            if (gr < NN) val = *(const float4*)(x + gr * FIN + kb + k4 * 4);
            *(float4*)&sx[r][k4 * 4] = val;
        }
        for (int idx = t; idx < 32 * 48; idx += 256) {
            int k = idx / 48, j = idx % 48;
            int gk = kb + k;
            float val;
            if (j < 16)      val = Wl[gk * 16 + j];
            else if (j < 32) val = Wr[gk * 16 + j - 16];
            else             val = Wlin[gk * 16 + j - 32];
            sw[k][j] = val;
        }
        __syncthreads();
#pragma unroll
        for (int k = 0; k < 32; k += 4) {
            float xv[4][4];
#pragma unroll
            for (int i = 0; i < 4; i++) {
                float4 tmp = *(const float4*)&sx[rg * 4 + i][k];
                xv[i][0] = tmp.x; xv[i][1] = tmp.y; xv[i][2] = tmp.z; xv[i][3] = tmp.w;
            }
#pragma unroll
            for (int kk = 0; kk < 4; kk++) {
                float wv[6];
#pragma unroll
                for (int j = 0; j < 6; j++) wv[j] = sw[k + kk][c0 + j];
#pragma unroll
                for (int i = 0; i < 4; i++)
#pragma unroll
                    for (int j = 0; j < 6; j++)
                        acc[i][j] = fmaf(xv[i][kk], wv[j], acc[i][j]);
            }
        }
        __syncthreads();
    }
#pragma unroll
    for (int i = 0; i < 4; i++) {
        int gr = rowbase + rg * 4 + i;
        if (gr < NN) {
#pragma unroll
            for (int j = 0; j < 6; j++) {
                int c = c0 + j;
                if (c < 16)      g_xl1[gr * 16 + c] = acc[i][j];
                else if (c < 32) g_xr1[gr * 16 + (c - 16)] = acc[i][j];
                else             g_lin1[gr * 16 + (c - 32)] = acc[i][j] + blin[c - 32];
            }
        }
    }
}

// ---------------- edge kernel layer 1: warp/node, 4 lanes/edge --------------
__global__ void __launch_bounds__(256) k_edge1(
    const float* __restrict__ att, const float* __restrict__ bias,
    const float* __restrict__ tptr)
{
    __shared__ float sm_p[8][CAP];
    int w = threadIdx.x >> 5;
    int lane = threadIdx.x & 31;
    int node = blockIdx.x * 8 + w;
    if (node >= NN) return;
    int q = lane & 3, e8 = lane >> 2;
    int deg = g_cnt[node];
    int degf = deg < CAP ? deg : CAP;
    const int* sp = g_srcs + node * CAP;
    float tl2e = tptr[0] * L2E;
    float4 a4 = *(const float4*)(att + q * 4);
    float4 xr = *(const float4*)(g_xr1 + node * 16 + q * 4);
    float a06x = 0.6f * L2E * a4.x, a06y = 0.6f * L2E * a4.y;
    float a06z = 0.6f * L2E * a4.z, a06w = 0.6f * L2E * a4.w;
    float a04x = 0.4f * L2E * a4.x, a04y = 0.4f * L2E * a4.y;
    float a04z = 0.4f * L2E * a4.z, a04w = 0.4f * L2E * a4.w;
    int nfull = degf >> 3, rem = degf & 7;

    float S = 0.f;
    int k = e8;
#pragma unroll 2
    for (int it = 0; it < nfull; it++, k += 8) {
        int s = sp[k];
        float4 m = *(const float4*)(g_xl1 + s * 16 + q * 4);
        float y0 = m.x + xr.x, y1 = m.y + xr.y, y2 = m.z + xr.z, y3 = m.w + xr.w;
        float sc = a06x * y0;
        sc = fmaf(a04x, fabsf(y0), sc);
        sc = fmaf(a06y, y1, sc); sc = fmaf(a04y, fabsf(y1), sc);
        sc = fmaf(a06z, y2, sc); sc = fmaf(a04z, fabsf(y2), sc);
        sc = fmaf(a06w, y3, sc); sc = fmaf(a04w, fabsf(y3), sc);
        sc += __shfl_xor_sync(0xffffffffu, sc, 1);
        sc += __shfl_xor_sync(0xffffffffu, sc, 2);
        float p = ex2f(sc);
        if (q == 0) sm_p[w][k] = p;
        S += p;
    }
    if (rem) {
        bool v = e8 < rem;
        int s = sp[v ? k : 0];
        float4 m = make_float4(0.f, 0.f, 0.f, 0.f);
        if (v) m = *(const float4*)(g_xl1 + s * 16 + q * 4);
        float y0 = m.x + xr.x, y1 = m.y + xr.y, y2 = m.z + xr.z, y3 = m.w + xr.w;
        float sc = a06x * y0;
        sc = fmaf(a04x, fabsf(y0), sc);
        sc = fmaf(a06y, y1, sc); sc = fmaf(a04y, fabsf(y1), sc);
        sc = fmaf(a06z, y2, sc); sc = fmaf(a04z, fabsf(y2), sc);
        sc = fmaf(a06w, y3, sc); sc = fmaf(a04w, fabsf(y3), sc);
        sc += __shfl_xor_sync(0xffffffffu, sc, 1);
        sc += __shfl_xor_sync(0xffffffffu, sc, 2);
        float p = v ? ex2f(sc) : 0.f;
        if (q == 0) sm_p[w][k] = p;
        S += p;
    }
    if (deg > CAP) {
        int ovfn = g_ovf_cnt;
        for (int i = 0; i < ovfn; i++) {
            if (g_ovfd[i] == node) {
                float4 m = make_float4(0.f, 0.f, 0.f, 0.f);
                if (e8 == 0) m = *(const float4*)(g_xl1 + g_ovfs[i] * 16 + q * 4);
                float y0 = m.x + xr.x, y1 = m.y + xr.y, y2 = m.z + xr.z, y3 = m.w + xr.w;
                float sc = a06x * y0;
                sc = fmaf(a04x, fabsf(y0), sc);
                sc = fmaf(a06y, y1, sc); sc = fmaf(a04y, fabsf(y1), sc);
                sc = fmaf(a06z, y2, sc); sc = fmaf(a04z, fabsf(y2), sc);
                sc = fmaf(a04w, fabsf(y3), fmaf(a06w, y3, sc));
                sc += __shfl_xor_sync(0xffffffffu, sc, 1);
                sc += __shfl_xor_sync(0xffffffffu, sc, 2);
                if (e8 == 0) S += ex2f(sc);
            }
        }
    }
#pragma unroll
    for (int o = 16; o; o >>= 1) S += __shfl_xor_sync(0xffffffffu, S, o);
    float rinv = __fdividef(4.f, S);   // S counted 4x per edge
    __syncwarp();

    float4 num = make_float4(0.f, 0.f, 0.f, 0.f);
    float4 den = make_float4(0.f, 0.f, 0.f, 0.f);
    k = e8;
#pragma unroll 2
    for (int it = 0; it < nfull; it++, k += 8) {
        int s = sp[k];
        float4 m = *(const float4*)(g_xl1 + s * 16 + q * 4);
        float p = sm_p[w][k];
        float a = p * rinv;
        float we = a * tl2e;
        float e0 = ex2f(m.x * we);
        float e1 = ex2f(m.y * we);
        float e2 = ex2f(m.z * we);
        float e3 = ex2f(m.w * we);
        den.x += e0; den.y += e1; den.z += e2; den.w += e3;
        num.x = fmaf(e0, m.x * a, num.x);
        num.y = fmaf(e1, m.y * a, num.y);
        num.z = fmaf(e2, m.z * a, num.z);
        num.w = fmaf(e3, m.w * a, num.w);
    }
    if (rem) {
        bool v = e8 < rem;
        float vm = v ? 1.f : 0.f;
        int s = sp[v ? k : 0];
        float4 m = make_float4(0.f, 0.f, 0.f, 0.f);
        if (v) m = *(const float4*)(g_xl1 + s * 16 + q * 4);
        float p = sm_p[w][k];
        float a = p * rinv;
        float we = a * tl2e;
        float e0 = ex2f(m.x * we) * vm;
        float e1 = ex2f(m.y * we) * vm;
        float e2 = ex2f(m.z * we) * vm;
        float e3 = ex2f(m.w * we) * vm;
        den.x += e0; den.y += e1; den.z += e2; den.w += e3;
        num.x = fmaf(e0, m.x * a, num.x);
        num.y = fmaf(e1, m.y * a, num.y);
        num.z = fmaf(e2, m.z * a, num.z);
        num.w = fmaf(e3, m.w * a, num.w);
    }
    if (deg > CAP) {
        int ovfn = g_ovf_cnt;
        for (int i = 0; i < ovfn; i++) {
            if (g_ovfd[i] == node) {
                float4 m = make_float4(0.f, 0.f, 0.f, 0.f);
                if (e8 == 0) m = *(const float4*)(g_xl1 + g_ovfs[i] * 16 + q * 4);
                float y0 = m.x + xr.x, y1 = m.y + xr.y, y2 = m.z + xr.z, y3 = m.w + xr.w;
                float sc = a06x * y0;
                sc = fmaf(a04x, fabsf(y0), sc);
                sc = fmaf(a06y, y1, sc); sc = fmaf(a04y, fabsf(y1), sc);
                sc = fmaf(a06z, y2, sc); sc = fmaf(a04z, fabsf(y2), sc);
                sc = fmaf(a04w, fabsf(y3), fmaf(a06w, y3, sc));
                sc += __shfl_xor_sync(0xffffffffu, sc, 1);
                sc += __shfl_xor_sync(0xffffffffu, sc, 2);
                if (e8 == 0) {
                    float p = ex2f(sc);
                    float a = p * rinv;
                    float we = a * tl2e;
                    float e0 = ex2f(m.x * we);
                    float e1 = ex2f(m.y * we);
                    float e2 = ex2f(m.z * we);
                    float e3 = ex2f(m.w * we);
                    den.x += e0; den.y += e1; den.z += e2; den.w += e3;
                    num.x = fmaf(e0, m.x * a, num.x);
                    num.y = fmaf(e1, m.y * a, num.y);
                    num.z = fmaf(e2, m.z * a, num.z);
                    num.w = fmaf(e3, m.w * a, num.w);
                }
            }
        }
    }
#pragma unroll
    for (int o = 4; o < 32; o <<= 1) {
        num.x += __shfl_xor_sync(0xffffffffu, num.x, o);
        num.y += __shfl_xor_sync(0xffffffffu, num.y, o);
        num.z += __shfl_xor_sync(0xffffffffu, num.z, o);
        num.w += __shfl_xor_sync(0xffffffffu, num.w, o);
        den.x += __shfl_xor_sync(0xffffffffu, den.x, o);
        den.y += __shfl_xor_sync(0xffffffffu, den.y, o);
        den.z += __shfl_xor_sync(0xffffffffu, den.z, o);
        den.w += __shfl_xor_sync(0xffffffffu, den.w, o);
    }
    if (e8 == 0) {
        float4 b4 = *(const float4*)(bias + q * 4);
        float4 l4 = *(const float4*)(g_lin1 + node * 16 + q * 4);
        float4 o4;
        float g0 = (den.x > 0.f) ? __fdividef(num.x, den.x) : 0.f;
        float g1 = (den.y > 0.f) ? __fdividef(num.y, den.y) : 0.f;
        float g2v = (den.z > 0.f) ? __fdividef(num.z, den.z) : 0.f;
        float g3 = (den.w > 0.f) ? __fdividef(num.w, den.w) : 0.f;
        o4.x = fmaxf(g0 + b4.x + l4.x, 0.f);
        o4.y = fmaxf(g1 + b4.y + l4.y, 0.f);
        o4.z = fmaxf(g2v + b4.z + l4.z, 0.f);
        o4.w = fmaxf(g3 + b4.w + l4.w, 0.f);
        *(float4*)(g_h + node * 16 + q * 4) = o4;
    }
}

// ---------------- layer-2 node GEMM (+ overflow counter hand-off) -----------
__global__ void __launch_bounds__(256) k_gemm2(
    const float* __restrict__ Wl, const float* __restrict__ Wr,
    const float* __restrict__ Wlin, const float* __restrict__ blin)
{
    if (blockIdx.x == 0 && threadIdx.x == 0) {
        g_ovf_cnt2 = g_ovf_cnt;
        g_ovf_cnt = 0;
    }
    __shared__ float sw[16 * 24];
    int t = threadIdx.x;
    for (int idx = t; idx < 16 * 24; idx += 256) {
        int k = idx / 24, j = idx % 24;
        float v;
        if (j < 8)       v = Wl[k * 8 + j];
        else if (j < 16) v = Wr[k * 8 + j - 8];
        else             v = Wlin[k * 8 + j - 16];
        sw[idx] = v;
    }
    __syncthreads();
    int i = blockIdx.x * blockDim.x + t;
    if (i >= NN) return;
    const float4* hp = (const float4*)(g_h + i * 16);
    float4 q0 = hp[0], q1 = hp[1], q2 = hp[2], q3 = hp[3];
    float h[16] = {q0.x, q0.y, q0.z, q0.w, q1.x, q1.y, q1.z, q1.w,
                   q2.x, q2.y, q2.z, q2.w, q3.x, q3.y, q3.z, q3.w};
    float acc[24];
#pragma unroll
    for (int j = 0; j < 24; j++) acc[j] = 0.f;
#pragma unroll
    for (int k = 0; k < 16; k++) {
        float hv = h[k];
#pragma unroll
        for (int j = 0; j < 24; j++) acc[j] = fmaf(hv, sw[k * 24 + j], acc[j]);
    }
#pragma unroll
    for (int j = 0; j < 8; j++) {
        g_xl2[i * 8 + j] = acc[j];
        g_xr2[i * 8 + j] = acc[8 + j];
        g_lin2[i * 8 + j] = acc[16 + j] + blin[j];
    }
}

// ------- edge kernel layer 2 (2 lanes/edge) + fused MLP head + log_sigmoid --
// Static reg cache m0..m2/p0..p2 with BATCHED pass-1 loads (MLP across groups).
__global__ void __launch_bounds__(256) k_edge2h(
    const float* __restrict__ att, const float* __restrict__ bias,
    const float* __restrict__ tptr,
    const float* __restrict__ W3, const float* __restrict__ b3,
    const float* __restrict__ W4, const float* __restrict__ b4,
    const float* __restrict__ W5, const float* __restrict__ b5,
    const float* __restrict__ Wout, const float* __restrict__ bout,
    float* __restrict__ out)
{
    __shared__ float sm_p[8][CAP];
    int w = threadIdx.x >> 5;
    int lane = threadIdx.x & 31;
    int node = blockIdx.x * 8 + w;
    if (node >= NN) return;
    int q = lane & 1, e16 = lane >> 1;
    int deg = g_cnt[node];
    if (lane == 0) g_cnt[node] = 0;   // reset for next launch
    int degf = deg < CAP ? deg : CAP;
    const int* sp = g_srcs + node * CAP;
    float tl2e = tptr[0] * L2E;
    float4 a4 = *(const float4*)(att + q * 4);
    float4 xr = *(const float4*)(g_xr2 + node * 8 + q * 4);
    float a06x = 0.6f * L2E * a4.x, a06y = 0.6f * L2E * a4.y;
    float a06z = 0.6f * L2E * a4.z, a06w = 0.6f * L2E * a4.w;
    float a04x = 0.4f * L2E * a4.x, a04y = 0.4f * L2E * a4.y;
    float a04z = 0.4f * L2E * a4.z, a04w = 0.4f * L2E * a4.w;
    int ngroups = (degf + 15) >> 4;   // groups of 16 edges

    // ---- pass 1 phase A: batched loads (indices then rows; max MLP) ----
    float4 m0 = make_float4(0.f, 0.f, 0.f, 0.f);
    float4 m1 = m0, m2 = m0;
    bool v0 = false, v1 = false, v2 = false;
    {
        int s0 = 0, s1 = 0, s2 = 0;
        if (0 < ngroups) { int kk = e16;      v0 = kk < degf; s0 = sp[v0 ? kk : 0]; }
        if (1 < ngroups) { int kk = 16 + e16; v1 = kk < degf; s1 = sp[v1 ? kk : 0]; }
        if (2 < ngroups) { int kk = 32 + e16; v2 = kk < degf; s2 = sp[v2 ? kk : 0]; }
        if (v0) m0 = *(const float4*)(g_xl2 + s0 * 8 + q * 4);
        if (v1) m1 = *(const float4*)(g_xl2 + s1 * 8 + q * 4);
        if (v2) m2 = *(const float4*)(g_xl2 + s2 * 8 + q * 4);
    }

    // ---- pass 1 phase B: scores (compute-only) ----
    float p0 = 0.f, p1 = 0.f, p2 = 0.f;
    float S = 0.f;
#define E2_SCORE(I, MI, PI, VI)                                              \
    if (I < ngroups) {                                                       \
        float y0 = MI.x + xr.x, y1 = MI.y + xr.y, y2 = MI.z + xr.z, y3 = MI.w + xr.w; \
        float sc = a06x * y0;                                                \
        sc = fmaf(a04x, fabsf(y0), sc);                                      \
        sc = fmaf(a06y, y1, sc); sc = fmaf(a04y, fabsf(y1), sc);             \
        sc = fmaf(a06z, y2, sc); sc = fmaf(a04z, fabsf(y2), sc);             \
        sc = fmaf(a06w, y3, sc); sc = fmaf(a04w, fabsf(y3), sc);             \
        sc += __shfl_xor_sync(0xffffffffu, sc, 1);                           \
        float p = VI ? ex2f(sc) : 0.f;                                       \
        PI = p; S += p;                                                      \
    }

    E2_SCORE(0, m0, p0, v0)
    E2_SCORE(1, m1, p1, v1)
    E2_SCORE(2, m2, p2, v2)
#undef E2_SCORE

    // ---- pass 1: groups >=3 via smem (deg in (48,128]) ----
    for (int it = 3; it < ngroups; it++) {
        int kk = it * 16 + e16;
        bool v = kk < degf;
        int s = sp[v ? kk : 0];
        float4 m = make_float4(0.f, 0.f, 0.f, 0.f);
        if (v) m = *(const float4*)(g_xl2 + s * 8 + q * 4);
        float y0 = m.x + xr.x, y1 = m.y + xr.y, y2 = m.z + xr.z, y3 = m.w + xr.w;
        float sc = a06x * y0;
        sc = fmaf(a04x, fabsf(y0), sc);
        sc = fmaf(a06y, y1, sc); sc = fmaf(a04y, fabsf(y1), sc);
        sc = fmaf(a06z, y2, sc); sc = fmaf(a04z, fabsf(y2), sc);
        sc = fmaf(a06w, y3, sc); sc = fmaf(a04w, fabsf(y3), sc);
        sc += __shfl_xor_sync(0xffffffffu, sc, 1);
        float p = v ? ex2f(sc) : 0.f;
        if (q == 0) sm_p[w][kk] = p;
        S += p;
    }
    // ---- pass 1: overflow list (cold) ----
    if (deg > CAP) {
        int ovfn = g_ovf_cnt2;
        for (int i = 0; i < ovfn; i++) {
            if (g_ovfd[i] == node) {
                float4 m = make_float4(0.f, 0.f, 0.f, 0.f);
                if (e16 == 0) m = *(const float4*)(g_xl2 + g_ovfs[i] * 8 + q * 4);
                float y0 = m.x + xr.x, y1 = m.y + xr.y, y2 = m.z + xr.z, y3 = m.w + xr.w;
                float sc = a06x * y0;
                sc = fmaf(a04x, fabsf(y0), sc);
                sc = fmaf(a06y, y1, sc); sc = fmaf(a04y, fabsf(y1), sc);
                sc = fmaf(a06z, y2, sc); sc = fmaf(a04z, fabsf(y2), sc);
                sc = fmaf(a04w, fabsf(y3), fmaf(a06w, y3, sc));
                sc += __shfl_xor_sync(0xffffffffu, sc, 1);
                if (e16 == 0) S += ex2f(sc);
            }
        }
    }
#pragma unroll
    for (int o = 16; o; o >>= 1) S += __shfl_xor_sync(0xffffffffu, S, o);
    float rinv = __fdividef(2.f, S);   // S counted 2x per edge
    __syncwarp();

    // ---- pass 2: groups 0..2 pure register math ----
    float4 num = make_float4(0.f, 0.f, 0.f, 0.f);
    float4 den = make_float4(0.f, 0.f, 0.f, 0.f);
#define E2_P2(I, MI, PI, VI)                                                 \
    if (I < ngroups) {                                                       \
        float vm = VI ? 1.f : 0.f;                                           \
        float a = PI * rinv;                                                 \
        float we = a * tl2e;                                                 \
        float e0 = ex2f(MI.x * we) * vm;                                     \
        float e1 = ex2f(MI.y * we) * vm;                                     \
        float e2 = ex2f(MI.z * we) * vm;                                     \
        float e3 = ex2f(MI.w * we) * vm;                                     \
        den.x += e0; den.y += e1; den.z += e2; den.w += e3;                  \
        num.x = fmaf(e0, MI.x * a, num.x);                                   \
        num.y = fmaf(e1, MI.y * a, num.y);                                   \
        num.z = fmaf(e2, MI.z * a, num.z);                                   \
        num.w = fmaf(e3, MI.w * a, num.w);                                   \
    }

    E2_P2(0, m0, p0, v0)
    E2_P2(1, m1, p1, v1)
    E2_P2(2, m2, p2, v2)
#undef E2_P2

    // ---- pass 2: groups >=3 re-gather + smem p ----
    for (int it = 3; it < ngroups; it++) {
        int kk = it * 16 + e16;
        bool v = kk < degf;
        float vm = v ? 1.f : 0.f;
        int s = sp[v ? kk : 0];
        float4 m = make_float4(0.f, 0.f, 0.f, 0.f);
        if (v) m = *(const float4*)(g_xl2 + s * 8 + q * 4);
        float p = sm_p[w][kk];
        float a = p * rinv;
        float we = a * tl2e;
        float e0 = ex2f(m.x * we) * vm;
        float e1 = ex2f(m.y * we) * vm;
        float e2 = ex2f(m.z * we) * vm;
        float e3 = ex2f(m.w * we) * vm;
        den.x += e0; den.y += e1; den.z += e2; den.w += e3;
        num.x = fmaf(e0, m.x * a, num.x);
        num.y = fmaf(e1, m.y * a, num.y);
        num.z = fmaf(e2, m.z * a, num.z);
        num.w = fmaf(e3, m.w * a, num.w);
    }
    // ---- pass 2: overflow list (cold) ----
    if (deg > CAP) {
        int ovfn = g_ovf_cnt2;
        for (int i = 0; i < ovfn; i++) {
            if (g_ovfd[i] == node) {
                float4 m = make_float4(0.f, 0.f, 0.f, 0.f);
                if (e16 == 0) m = *(const float4*)(g_xl2 + g_ovfs[i] * 8 + q * 4);
                float y0 = m.x + xr.x, y1 = m.y + xr.y, y2 = m.z + xr.z, y3 = m.w + xr.w;
                float sc = a06x * y0;
                sc = fmaf(a04x, fabsf(y0), sc);
                sc = fmaf(a06y, y1, sc); sc = fmaf(a04y, fabsf(y1), sc);
                sc = fmaf(a06z, y2, sc); sc = fmaf(a04z, fabsf(y2), sc);
                sc = fmaf(a04w, fabsf(y3), fmaf(a06w, y3, sc));
                sc += __shfl_xor_sync(0xffffffffu, sc, 1);
                if (e16 == 0) {
                    float p = ex2f(sc);
                    float a = p * rinv;
                    float we = a * tl2e;
                    float e0 = ex2f(m.x * we);
                    float e1 = ex2f(m.y * we);
                    float e2 = ex2f(m.z * we);
                    float e3 = ex2f(m.w * we);
                    den.x += e0; den.y += e1; den.z += e2; den.w += e3;
                    num.x = fmaf(e0, m.x * a, num.x);
                    num.y = fmaf(e1, m.y * a, num.y);
                    num.z = fmaf(e2, m.z * a, num.z);
                    num.w = fmaf(e3, m.w * a, num.w);
                }
            }
        }
    }
#pragma unroll
    for (int o = 2; o < 32; o <<= 1) {
        num.x += __shfl_xor_sync(0xffffffffu, num.x, o);
        num.y += __shfl_xor_sync(0xffffffffu, num.y, o);
        num.z += __shfl_xor_sync(0xffffffffu, num.z, o);
        num.w += __shfl_xor_sync(0xffffffffu, num.w, o);
        den.x += __shfl_xor_sync(0xffffffffu, den.x, o);
        den.y += __shfl_xor_sync(0xffffffffu, den.y, o);
        den.z += __shfl_xor_sync(0xffffffffu, den.z, o);
        den.w += __shfl_xor_sync(0xffffffffu, den.w, o);
    }

    // ---- fused head: lanes pair via q ----
    float4 b4v = *(const float4*)(bias + q * 4);
    float4 l4 = *(const float4*)(g_lin2 + node * 8 + q * 4);
    float hq[4];
    {
        float g0 = (den.x > 0.f) ? __fdividef(num.x, den.x) : 0.f;
        float g1 = (den.y > 0.f) ? __fdividef(num.y, den.y) : 0.f;
        float g2v = (den.z > 0.f) ? __fdividef(num.z, den.z) : 0.f;
        float g3 = (den.w > 0.f) ? __fdividef(num.w, den.w) : 0.f;
        hq[0] = fmaxf(g0 + b4v.x + l4.x, 0.f);
        hq[1] = fmaxf(g1 + b4v.y + l4.y, 0.f);
        hq[2] = fmaxf(g2v + b4v.z + l4.z, 0.f);
        hq[3] = fmaxf(g3 + b4v.w + l4.w, 0.f);
    }
    float part[8];
#pragma unroll
    for (int c = 0; c < 8; c++) {
        float acc = 0.f;
#pragma unroll
        for (int j = 0; j < 4; j++)
            acc = fmaf(hq[j], W3[(4 * q + j) * 8 + c], acc);
        part[c] = acc;
    }
#pragma unroll
    for (int c = 0; c < 8; c++)
        part[c] += __shfl_xor_sync(0xffffffffu, part[c], 1);
    if (lane == 0) {
        float s4 = b4[0];
#pragma unroll
        for (int c = 0; c < 8; c++) {
            float z = part[c] + b3[c];
            z = z > 0.f ? z : 0.f;
            s4 = fmaf(z, W4[c], s4);
        }
        s4 = s4 > 0.f ? s4 : 0.f;
        float s5 = W5[0] * s4 + b5[0];
        s5 = s5 > 0.f ? s5 : 0.f;
        float xo = Wout[0] * s5 + bout[0];
        float ls = (xo >= 0.f) ? -log1pf(expf(-xo)) : (xo - log1pf(expf(xo)));
        out[node] = ls;
    }
}

// ---------------- launch ----------------
extern "C" void kernel_launch(void* const* d_in, const int* in_sizes, int n_in,
                              void* d_out, int out_size)
{
    const float* x    = (const float*)d_in[0];
    const int*   ei   = (const int*)d_in[1];
    const int*   src  = ei;
    const int*   dst  = ei + EE;
    const float* Wl1  = (const float*)d_in[3];
    const float* Wr1  = (const float*)d_in[4];
    const float* att1 = (const float*)d_in[5];
    const float* b1   = (const float*)d_in[6];
    const float* Wlin1= (const float*)d_in[7];
    const float* blin1= (const float*)d_in[8];
    const float* Wl2  = (const float*)d_in[9];
    const float* Wr2  = (const float*)d_in[10];
    const float* att2 = (const float*)d_in[11];
    const float* b2   = (const float*)d_in[12];
    const float* Wlin2= (const float*)d_in[13];
    const float* blin2= (const float*)d_in[14];
    const float* t    = (const float*)d_in[15];
    const float* W3   = (const float*)d_in[16];
    const float* b3   = (const float*)d_in[17];
    const float* W4   = (const float*)d_in[18];
    const float* b4   = (const float*)d_in[19];
    const float* W5   = (const float*)d_in[20];
    const float* b5   = (const float*)d_in[21];
    const float* Wout = (const float*)d_in[22];
    const float* bout = (const float*)d_in[23];
    float* out = (float*)d_out;

    // 0: fused layer-1 GEMM + MLP-8 bucket scatter
    k_build<<<GEMM1_BLKS + HIST_BLKS, 256>>>(src, dst, x, Wl1, Wr1, Wlin1, blin1);
    // 1: edge layer 1
    k_edge1<<<(NN + 7) / 8, 256>>>(att1, b1, t);
    // 2: layer-2 GEMM (pool is identity) + overflow counter hand-off
    k_gemm2<<<(NN + 255) / 256, 256>>>(Wl2, Wr2, Wlin2, blin2);
    // 3: edge layer 2 + fused MLP head (batched pass-1 loads)
    k_edge2h<<<(NN + 7) / 8, 256>>>(att2, b2, t, W3, b3, W4, b4, W5, b5, Wout, bout, out);
}